// round 1
// baseline (speedup 1.0000x reference)
#include <cuda_runtime.h>

#define S 64
#define D 128
#define ALPHA 0.2f

__global__ void __launch_bounds__(256, 4)
gat_kernel(const float* __restrict__ center,
           const float* __restrict__ nbr,
           const float* __restrict__ a,
           float* __restrict__ out)
{
    __shared__ float s_nbr[S * D];   // 32 KB: neighbor tile kept for pooling
    __shared__ float s_e[S];
    __shared__ float s_w[S];
    __shared__ float s_part[D];

    const int n    = blockIdx.x;
    const int tid  = threadIdx.x;
    const int warp = tid >> 5;
    const int lane = tid & 31;

    // a is [2D,1]: a1 = a[0:128] pairs with center, a2 = a[128:256] with nbr.
    // Each lane holds a float4 slice of each half.
    const float4 a1 = reinterpret_cast<const float4*>(a)[lane];
    const float4 a2 = reinterpret_cast<const float4*>(a)[32 + lane];

    const float* __restrict__ cbase = center + (size_t)n * (S * D);
    const float* __restrict__ nbase = nbr    + (size_t)n * (S * D);

    // Phase 1: each warp computes 8 logits; nbr rows parked in smem.
    #pragma unroll
    for (int i = 0; i < 8; i++) {
        const int row = warp * 8 + i;
        const float4 c = reinterpret_cast<const float4*>(cbase + row * D)[lane];
        const float4 v = reinterpret_cast<const float4*>(nbase + row * D)[lane];
        reinterpret_cast<float4*>(s_nbr + row * D)[lane] = v;

        float sum = c.x * a1.x + c.y * a1.y + c.z * a1.z + c.w * a1.w
                  + v.x * a2.x + v.y * a2.y + v.z * a2.z + v.w * a2.w;
        #pragma unroll
        for (int off = 16; off; off >>= 1)
            sum += __shfl_xor_sync(0xffffffffu, sum, off);
        if (lane == 0) s_e[row] = sum;
    }
    __syncthreads();

    // Phase 2: warp 0 does leaky_relu + softmax over the 64 logits.
    if (warp == 0) {
        float e0 = s_e[lane];
        float e1 = s_e[lane + 32];
        e0 = (e0 > 0.f) ? e0 : ALPHA * e0;
        e1 = (e1 > 0.f) ? e1 : ALPHA * e1;
        float m = fmaxf(e0, e1);
        #pragma unroll
        for (int off = 16; off; off >>= 1)
            m = fmaxf(m, __shfl_xor_sync(0xffffffffu, m, off));
        const float x0 = __expf(e0 - m);
        const float x1 = __expf(e1 - m);
        float sm = x0 + x1;
        #pragma unroll
        for (int off = 16; off; off >>= 1)
            sm += __shfl_xor_sync(0xffffffffu, sm, off);
        const float inv = __frcp_rn(sm);
        s_w[lane]      = x0 * inv;
        s_w[lane + 32] = x1 * inv;
    }
    __syncthreads();

    // Phase 3: weighted pooling. 256 threads = (2 halves of S) x (128 d's).
    const int d = tid & (D - 1);
    const int h = tid >> 7;           // 0 or 1: which 32-neighbor half
    float acc = 0.f;
    #pragma unroll
    for (int i = 0; i < 32; i++) {
        const int s = h * 32 + i;
        acc += s_w[s] * s_nbr[s * D + d];
    }
    if (h == 1) s_part[d] = acc;
    __syncthreads();
    if (h == 0) out[(size_t)n * D + d] = acc + s_part[d];
}

extern "C" void kernel_launch(void* const* d_in, const int* in_sizes, int n_in,
                              void* d_out, int out_size)
{
    const float* center = (const float*)d_in[0];
    const float* nbr    = (const float*)d_in[1];
    const float* a      = (const float*)d_in[2];
    float* out          = (float*)d_out;

    const int n_groups = in_sizes[0] / (S * D);   // 8192
    gat_kernel<<<n_groups, 256>>>(center, nbr, a, out);
}

// round 2
// speedup vs baseline: 1.0223x; 1.0223x over previous
#include <cuda_runtime.h>
#include <math_constants.h>

#define S 64
#define D 128
#define ALPHA 0.2f
#define NWARP 8

__global__ void __launch_bounds__(256, 6)
gat_kernel(const float* __restrict__ center,
           const float* __restrict__ nbr,
           const float* __restrict__ a,
           float* __restrict__ out)
{
    __shared__ float s_m[NWARP];
    __shared__ float s_sum[NWARP];
    __shared__ float s_acc[NWARP][D];   // 4 KB

    const int n    = blockIdx.x;
    const int tid  = threadIdx.x;
    const int warp = tid >> 5;
    const int lane = tid & 31;

    // a[0:128] pairs with center, a[128:256] with nbr; float4 slice per lane.
    const float4 a1 = reinterpret_cast<const float4*>(a)[lane];
    const float4 a2 = reinterpret_cast<const float4*>(a)[32 + lane];

    // Each warp owns 8 consecutive neighbor rows.
    const float4* __restrict__ cvec =
        reinterpret_cast<const float4*>(center) + (size_t)n * (S * D / 4) + warp * 8 * 32;
    const float4* __restrict__ nvec =
        reinterpret_cast<const float4*>(nbr)    + (size_t)n * (S * D / 4) + warp * 8 * 32;

    // Online softmax accumulation: one pass, v never leaves registers.
    float m  = -CUDART_INF_F;
    float sm = 0.f;
    float4 acc = make_float4(0.f, 0.f, 0.f, 0.f);

    #pragma unroll
    for (int i = 0; i < 8; i++) {
        const float4 c = cvec[i * 32 + lane];
        const float4 v = nvec[i * 32 + lane];

        float e = c.x * a1.x + c.y * a1.y + c.z * a1.z + c.w * a1.w
                + v.x * a2.x + v.y * a2.y + v.z * a2.z + v.w * a2.w;
        #pragma unroll
        for (int off = 16; off; off >>= 1)
            e += __shfl_xor_sync(0xffffffffu, e, off);   // all lanes hold full dot

        e = (e > 0.f) ? e : ALPHA * e;                    // leaky relu

        const float nm    = fmaxf(m, e);
        const float scale = __expf(m - nm);               // first iter: exp(-inf)=0
        const float p     = __expf(e - nm);
        sm = sm * scale + p;
        acc.x = acc.x * scale + p * v.x;
        acc.y = acc.y * scale + p * v.y;
        acc.z = acc.z * scale + p * v.z;
        acc.w = acc.w * scale + p * v.w;
        m = nm;
    }

    if (lane == 0) { s_m[warp] = m; s_sum[warp] = sm; }
    reinterpret_cast<float4*>(s_acc[warp])[lane] = acc;
    __syncthreads();

    // Cross-warp combine: 128 threads, one output feature each.
    if (tid < D) {
        float M = s_m[0];
        #pragma unroll
        for (int w = 1; w < NWARP; w++) M = fmaxf(M, s_m[w]);

        float tot = 0.f, o = 0.f;
        #pragma unroll
        for (int w = 0; w < NWARP; w++) {
            const float f = __expf(s_m[w] - M);
            tot += s_sum[w] * f;
            o   += s_acc[w][tid] * f;
        }
        out[(size_t)n * D + tid] = o * __frcp_rn(tot);
    }
}

extern "C" void kernel_launch(void* const* d_in, const int* in_sizes, int n_in,
                              void* d_out, int out_size)
{
    const float* center = (const float*)d_in[0];
    const float* nbr    = (const float*)d_in[1];
    const float* a      = (const float*)d_in[2];
    float* out          = (float*)d_out;

    const int n_groups = in_sizes[0] / (S * D);   // 8192
    gat_kernel<<<n_groups, 256>>>(center, nbr, a, out);
}

// round 3
// speedup vs baseline: 1.0235x; 1.0011x over previous
#include <cuda_runtime.h>

#define S 64
#define D 128
#define ALPHA 0.2f
#define NWARP 8

__global__ void __launch_bounds__(256, 4)
gat_kernel(const float* __restrict__ center,
           const float* __restrict__ nbr,
           const float* __restrict__ a,
           float* __restrict__ out)
{
    __shared__ float s_m[NWARP];
    __shared__ float s_sum[NWARP];
    __shared__ float s_acc[NWARP][D];   // 4 KB

    const int n    = blockIdx.x;
    const int tid  = threadIdx.x;
    const int warp = tid >> 5;
    const int lane = tid & 31;

    // a[0:128] pairs with center, a[128:256] with nbr; float4 slice per lane.
    const float4 a1 = reinterpret_cast<const float4*>(a)[lane];
    const float4 a2 = reinterpret_cast<const float4*>(a)[32 + lane];

    const float4* __restrict__ cvec =
        reinterpret_cast<const float4*>(center) + (size_t)n * (S * D / 4) + warp * 8 * 32;
    const float4* __restrict__ nvec =
        reinterpret_cast<const float4*>(nbr)    + (size_t)n * (S * D / 4) + warp * 8 * 32;

    // ---- Phase 1: burst-load 8 c rows + 8 v rows; partial dots per lane. ----
    float4 v[8];
    float  d[8];
    #pragma unroll
    for (int i = 0; i < 8; i++) {
        const float4 c = __ldcs(&cvec[i * 32 + lane]);
        v[i]           = __ldcs(&nvec[i * 32 + lane]);
        d[i] = c.x * a1.x + c.y * a1.y + c.z * a1.z + c.w * a1.w
             + v[i].x * a2.x + v[i].y * a2.y + v[i].z * a2.z + v[i].w * a2.w;
    }

    // ---- Phase 2: butterfly-reduce all 8 dots (off the load path). ----
    #pragma unroll
    for (int i = 0; i < 8; i++) {
        #pragma unroll
        for (int off = 16; off; off >>= 1)
            d[i] += __shfl_xor_sync(0xffffffffu, d[i], off);
    }

    // ---- Phase 3: per-warp softmax over 8 logits (all lanes have totals). ----
    float m = -1e30f;
    #pragma unroll
    for (int i = 0; i < 8; i++) {
        d[i] = (d[i] > 0.f) ? d[i] : ALPHA * d[i];   // leaky relu
        m = fmaxf(m, d[i]);
    }
    float sm = 0.f;
    float4 acc = make_float4(0.f, 0.f, 0.f, 0.f);
    #pragma unroll
    for (int i = 0; i < 8; i++) {
        const float p = __expf(d[i] - m);
        sm += p;
        acc.x += p * v[i].x;
        acc.y += p * v[i].y;
        acc.z += p * v[i].z;
        acc.w += p * v[i].w;
    }

    if (lane == 0) { s_m[warp] = m; s_sum[warp] = sm; }
    reinterpret_cast<float4*>(s_acc[warp])[lane] = acc;
    __syncthreads();

    // ---- Phase 4: cross-warp combine; 128 threads, one feature each. ----
    if (tid < D) {
        float M = s_m[0];
        #pragma unroll
        for (int w = 1; w < NWARP; w++) M = fmaxf(M, s_m[w]);

        float tot = 0.f, o = 0.f;
        #pragma unroll
        for (int w = 0; w < NWARP; w++) {
            const float f = __expf(s_m[w] - M);
            tot += s_sum[w] * f;
            o   += s_acc[w][tid] * f;
        }
        out[(size_t)n * D + tid] = o * __frcp_rn(tot);
    }
}

extern "C" void kernel_launch(void* const* d_in, const int* in_sizes, int n_in,
                              void* d_out, int out_size)
{
    const float* center = (const float*)d_in[0];
    const float* nbr    = (const float*)d_in[1];
    const float* a      = (const float*)d_in[2];
    float* out          = (float*)d_out;

    const int n_groups = in_sizes[0] / (S * D);   // 8192
    gat_kernel<<<n_groups, 256>>>(center, nbr, a, out);
}